// round 12
// baseline (speedup 1.0000x reference)
#include <cuda_runtime.h>
#include <cuda_fp16.h>

#define BATCH 128
#define DG 512
#define DH 1024
#define LAM 0.95f
#define ETA 0.5f
#define LN_EPS 1e-5f

// Scratch (allocation-free)
__device__ float  g_base[BATCH * DH];
__device__ float  g_y0[BATCH * DH];
__device__ float  g_y1[BATCH * DH];
__device__ __half g_Ah[(size_t)BATCH * DH * DH];   // fp16 copy of A (268MB)

// ---------------------------------------------------------------------------
__device__ __forceinline__ float2 pack_h4(float4 v) {
    __half2 a = __floats2half2_rn(v.x, v.y);
    __half2 b = __floats2half2_rn(v.z, v.w);
    float2 r;
    r.x = __uint_as_float(*reinterpret_cast<unsigned int*>(&a));
    r.y = __uint_as_float(*reinterpret_cast<unsigned int*>(&b));
    return r;
}

__device__ __forceinline__ float dot8(uint4 v, float4 ha, float4 hb) {
    const __half2* p = reinterpret_cast<const __half2*>(&v);
    float2 f0 = __half22float2(p[0]);
    float2 f1 = __half22float2(p[1]);
    float2 f2 = __half22float2(p[2]);
    float2 f3 = __half22float2(p[3]);
    return f0.x * ha.x + f0.y * ha.y + f1.x * ha.z + f1.y * ha.w
         + f2.x * hb.x + f2.y * hb.y + f3.x * hb.z + f3.y * hb.w;
}

// unpack 4 halfs (uint2) to float4
__device__ __forceinline__ float4 unpack_h4(uint2 v) {
    __half2 lo = *reinterpret_cast<__half2*>(&v.x);
    __half2 hi = *reinterpret_cast<__half2*>(&v.y);
    float2 f0 = __half22float2(lo);
    float2 f1 = __half22float2(hi);
    float4 r; r.x = f0.x; r.y = f0.y; r.z = f1.x; r.w = f1.y;
    return r;
}

// ---------------------------------------------------------------------------
// Kernel 1: base = h_prev@Wh^T + z@Wg^T + bh.
// ---------------------------------------------------------------------------
__global__ void base_gemm_kernel(const float* __restrict__ Hp,
                                 const float* __restrict__ Z,
                                 const float* __restrict__ Wh,
                                 const float* __restrict__ Wg,
                                 const float* __restrict__ bh)
{
    __shared__ float Hs[32][33];
    __shared__ float Ws[32][33];

    const int tid = threadIdx.x;
    const int tx = tid & 15;
    const int ty = tid >> 4;
    const int bm0 = blockIdx.x * 32;
    const int n0  = blockIdx.y * 32;

    float acc00 = 0.f, acc01 = 0.f, acc10 = 0.f, acc11 = 0.f;

    for (int k0 = 0; k0 < DH + DG; k0 += 32) {
        const float* src;
        const float* wsrc;
        int K, kk0;
        if (k0 < DH) { src = Hp; wsrc = Wh; K = DH; kk0 = k0; }
        else         { src = Z;  wsrc = Wg; K = DG; kk0 = k0 - DH; }

        #pragma unroll
        for (int l = 0; l < 4; l++) {
            int idx = tid + l * 256;
            int r = idx >> 5, c = idx & 31;
            Hs[r][c] = src[(bm0 + r) * K + kk0 + c];
            Ws[r][c] = wsrc[(n0 + r) * K + kk0 + c];
        }
        __syncthreads();

        #pragma unroll
        for (int kk = 0; kk < 32; kk++) {
            float h0 = Hs[ty * 2][kk];
            float h1 = Hs[ty * 2 + 1][kk];
            float w0 = Ws[tx * 2][kk];
            float w1 = Ws[tx * 2 + 1][kk];
            acc00 += h0 * w0; acc01 += h0 * w1;
            acc10 += h1 * w0; acc11 += h1 * w1;
        }
        __syncthreads();
    }

    const int r0 = bm0 + ty * 2;
    const int c0 = n0 + tx * 2;
    const float bias0 = bh[c0];
    const float bias1 = bh[c0 + 1];
    g_base[r0 * DH + c0]           = acc00 + bias0;
    g_base[r0 * DH + c0 + 1]       = acc01 + bias1;
    g_base[(r0 + 1) * DH + c0]     = acc10 + bias0;
    g_base[(r0 + 1) * DH + c0 + 1] = acc11 + bias1;
}

// ---------------------------------------------------------------------------
// In-block LN+ReLU: 256 threads, h[b] (1024 floats) into s_h. Trailing sync.
// ---------------------------------------------------------------------------
__device__ __forceinline__ void compute_h(const float* __restrict__ base_b,
                                          const float* __restrict__ y_b,
                                          const float* __restrict__ gamma,
                                          const float* __restrict__ beta,
                                          float* __restrict__ s_h,
                                          float* __restrict__ s_red,
                                          int t)
{
    const int w = t >> 5, lane = t & 31;

    float4 x = reinterpret_cast<const float4*>(base_b)[t];
    if (y_b) {
        float4 y = reinterpret_cast<const float4*>(y_b)[t];
        x.x += y.x; x.y += y.y; x.z += y.z; x.w += y.w;
    }
    float s  = (x.x + x.y) + (x.z + x.w);
    float ss = fmaf(x.x, x.x, x.y * x.y) + fmaf(x.z, x.z, x.w * x.w);

    #pragma unroll
    for (int o = 16; o > 0; o >>= 1) {
        s  += __shfl_xor_sync(0xffffffffu, s,  o);
        ss += __shfl_xor_sync(0xffffffffu, ss, o);
    }
    if (lane == 0) { s_red[w] = s; s_red[8 + w] = ss; }
    __syncthreads();
    if (t < 32) {
        float a = (lane < 8) ? s_red[lane]     : 0.f;
        float c = (lane < 8) ? s_red[8 + lane] : 0.f;
        #pragma unroll
        for (int o = 4; o > 0; o >>= 1) {
            a += __shfl_xor_sync(0xffffffffu, a, o);
            c += __shfl_xor_sync(0xffffffffu, c, o);
        }
        if (lane == 0) { s_red[0] = a; s_red[1] = c; }
    }
    __syncthreads();

    const float mu   = s_red[0] * (1.0f / DH);
    const float var  = s_red[1] * (1.0f / DH) - mu * mu;
    const float rstd = rsqrtf(var + LN_EPS);

    float4 g  = reinterpret_cast<const float4*>(gamma)[t];
    float4 be = reinterpret_cast<const float4*>(beta)[t];
    float4 h;
    h.x = fmaxf(0.f, (x.x - mu) * rstd * g.x + be.x);
    h.y = fmaxf(0.f, (x.y - mu) * rstd * g.y + be.y);
    h.z = fmaxf(0.f, (x.z - mu) * rstd * g.z + be.z);
    h.w = fmaxf(0.f, (x.w - mu) * rstd * g.w + be.w);
    reinterpret_cast<float4*>(s_h)[t] = h;
    __syncthreads();
}

// ---------------------------------------------------------------------------
// Kernel 2: mv1 + fp16 conversion. Ascending batch order; fp16 copy written
// with NORMAL stores (evict-normal) so the tail stays L2-resident for mv2.
// fp32 A reads stay __ldcs (pure stream, never reused).
// grid = (16 chunks, 128 batches), 256 thr.
// ---------------------------------------------------------------------------
__global__ __launch_bounds__(256)
void matvec_conv_kernel(const float* __restrict__ A,
                        float* __restrict__ yout,
                        const float* __restrict__ gamma,
                        const float* __restrict__ beta)
{
    __shared__ float s_h[DH];
    __shared__ float s_red[16];

    const int b = blockIdx.y;
    const int chunk = blockIdx.x;
    const int t = threadIdx.x;
    const int w = t >> 5, lane = t & 31;

    compute_h(g_base + b * DH, nullptr, gamma, beta, s_h, s_red, t);

    const float4* __restrict__ Ab =
        reinterpret_cast<const float4*>(A + (size_t)b * DH * DH);
    const float4* h4 = reinterpret_cast<const float4*>(s_h);

    #pragma unroll
    for (int g = 0; g < 2; g++) {
        const int r0 = chunk * 64 + w * 8 + g * 4;
        const float4* Ar0 = Ab + (size_t)r0 * 256;
        float2* __restrict__ Oh0 =
            reinterpret_cast<float2*>(g_Ah + ((size_t)b * DH + r0) * DH);

        float a0 = 0.f, a1 = 0.f, a2 = 0.f, a3 = 0.f;
        #pragma unroll
        for (int it = 0; it < 8; it++) {
            float4 v0 = __ldcs(Ar0 + lane + it * 32);
            float4 v1 = __ldcs(Ar0 + 256 + lane + it * 32);
            float4 v2 = __ldcs(Ar0 + 512 + lane + it * 32);
            float4 v3 = __ldcs(Ar0 + 768 + lane + it * 32);
            float4 hv = h4[lane + it * 32];
            a0 += v0.x * hv.x + v0.y * hv.y + v0.z * hv.z + v0.w * hv.w;
            a1 += v1.x * hv.x + v1.y * hv.y + v1.z * hv.z + v1.w * hv.w;
            a2 += v2.x * hv.x + v2.y * hv.y + v2.z * hv.z + v2.w * hv.w;
            a3 += v3.x * hv.x + v3.y * hv.y + v3.z * hv.z + v3.w * hv.w;
            // normal (evict-normal) stores: allocate in L2 for the consumer
            Oh0[lane + it * 32]       = pack_h4(v0);
            Oh0[256 + lane + it * 32] = pack_h4(v1);
            Oh0[512 + lane + it * 32] = pack_h4(v2);
            Oh0[768 + lane + it * 32] = pack_h4(v3);
        }
        #pragma unroll
        for (int o = 16; o > 0; o >>= 1) {
            a0 += __shfl_xor_sync(0xffffffffu, a0, o);
            a1 += __shfl_xor_sync(0xffffffffu, a1, o);
            a2 += __shfl_xor_sync(0xffffffffu, a2, o);
            a3 += __shfl_xor_sync(0xffffffffu, a3, o);
        }
        if (lane == 0) {
            yout[b * DH + r0]     = a0;
            yout[b * DH + r0 + 1] = a1;
            yout[b * DH + r0 + 2] = a2;
            yout[b * DH + r0 + 3] = a3;
        }
    }
}

// ---------------------------------------------------------------------------
// Kernel 3 (x2): fp16 matvec. h = relu(LN(base + yin)); yout = Ah@h.
// rev selects batch iteration order so each launch starts on the part of
// g_Ah the previous kernel left resident in L2. Loads are __ldg
// (evict-normal) so THIS kernel's tail stays resident for the next one.
// grid = (32 chunks of 32 rows, 128 batches), 256 thr.
// ---------------------------------------------------------------------------
__global__ __launch_bounds__(256)
void matvec_h_kernel(const float* __restrict__ yin,
                     float* __restrict__ yout,
                     const float* __restrict__ gamma,
                     const float* __restrict__ beta,
                     int rev)
{
    __shared__ float s_h[DH];
    __shared__ float s_red[16];

    const int b = rev ? (BATCH - 1 - blockIdx.y) : blockIdx.y;
    const int chunk = blockIdx.x;
    const int t = threadIdx.x;
    const int w = t >> 5, lane = t & 31;

    compute_h(g_base + b * DH, yin + b * DH, gamma, beta, s_h, s_red, t);

    const float4* h4 = reinterpret_cast<const float4*>(s_h);

    const int r0 = chunk * 32 + w * 4;
    const uint4* __restrict__ R0 =
        reinterpret_cast<const uint4*>(g_Ah + ((size_t)b * DH + r0) * DH);

    float a0 = 0.f, a1 = 0.f, a2 = 0.f, a3 = 0.f;
    #pragma unroll
    for (int it = 0; it < 4; it++) {
        uint4 v0 = __ldg(R0 + lane + it * 32);
        uint4 v1 = __ldg(R0 + 128 + lane + it * 32);
        uint4 v2 = __ldg(R0 + 256 + lane + it * 32);
        uint4 v3 = __ldg(R0 + 384 + lane + it * 32);
        const int idx = (it * 32 + lane) * 2;
        float4 ha = h4[idx];
        float4 hb = h4[idx + 1];
        a0 += dot8(v0, ha, hb);
        a1 += dot8(v1, ha, hb);
        a2 += dot8(v2, ha, hb);
        a3 += dot8(v3, ha, hb);
    }
    #pragma unroll
    for (int o = 16; o > 0; o >>= 1) {
        a0 += __shfl_xor_sync(0xffffffffu, a0, o);
        a1 += __shfl_xor_sync(0xffffffffu, a1, o);
        a2 += __shfl_xor_sync(0xffffffffu, a2, o);
        a3 += __shfl_xor_sync(0xffffffffu, a3, o);
    }
    if (lane == 0) {
        yout[b * DH + r0]     = a0;
        yout[b * DH + r0 + 1] = a1;
        yout[b * DH + r0 + 2] = a2;
        yout[b * DH + r0 + 3] = a3;
    }
}

// ---------------------------------------------------------------------------
// Kernel 4: h3 = relu(LN(base + yin)) written straight into outH.
// ---------------------------------------------------------------------------
__global__ __launch_bounds__(256)
void h_final_kernel(const float* __restrict__ yin,
                    const float* __restrict__ gamma,
                    const float* __restrict__ beta,
                    float* __restrict__ outH)
{
    __shared__ float s_h[DH];
    __shared__ float s_red[16];
    const int b = blockIdx.x;
    const int t = threadIdx.x;

    compute_h(g_base + b * DH, yin + b * DH, gamma, beta, s_h, s_red, t);
    reinterpret_cast<float4*>(outH + b * DH)[t] =
        reinterpret_cast<const float4*>(s_h)[t];
}

// ---------------------------------------------------------------------------
// Kernel 5: pure-stream Hebbian update from fp16 A. Coalesced uint2 loads
// at +t (__ldcs: last consumer), coalesced float4 stores at +t (__stcs).
// DESCENDING batch order to start on mv3's L2-resident tail.
// grid = (128 chunks of 8 rows, 128 batches), 256 thr, loads upfront.
// ---------------------------------------------------------------------------
__global__ __launch_bounds__(256)
void update_stream_kernel(const float* __restrict__ h3,   // = outH
                          float* __restrict__ outA)
{
    const int b = BATCH - 1 - blockIdx.y;
    const int chunk = blockIdx.x;
    const int t = threadIdx.x;
    const int row0 = chunk * 8;

    const uint2* __restrict__ Ab =
        reinterpret_cast<const uint2*>(g_Ah + (size_t)b * DH * DH) +
        (size_t)row0 * 256;                       // 256 uint2 per row
    float4* __restrict__ Ob =
        reinterpret_cast<float4*>(outA + (size_t)b * DH * DH) +
        (size_t)row0 * 256;

    const float4 hv = __ldg(reinterpret_cast<const float4*>(h3 + b * DH) + t);

    float hr[8];
    #pragma unroll
    for (int r = 0; r < 8; r++)
        hr[r] = __ldg(h3 + b * DH + row0 + r) * ETA;

    // issue all 8 independent row loads up front
    uint2 c[8];
    #pragma unroll
    for (int r = 0; r < 8; r++)
        c[r] = __ldcs(Ab + (size_t)r * 256 + t);

    // drain: unpack, fma, store (stores contiguous at +t per row)
    #pragma unroll
    for (int r = 0; r < 8; r++) {
        float4 a = unpack_h4(c[r]);
        const float hi = hr[r];
        float4 o;
        o.x = fmaf(LAM, a.x, hi * hv.x);
        o.y = fmaf(LAM, a.y, hi * hv.y);
        o.z = fmaf(LAM, a.z, hi * hv.z);
        o.w = fmaf(LAM, a.w, hi * hv.w);
        __stcs(Ob + (size_t)r * 256 + t, o);
    }
}

// ---------------------------------------------------------------------------
extern "C" void kernel_launch(void* const* d_in, const int* in_sizes, int n_in,
                              void* d_out, int out_size)
{
    const float* z      = (const float*)d_in[0];
    const float* h_prev = (const float*)d_in[1];
    const float* A_prev = (const float*)d_in[2];
    const float* W_h    = (const float*)d_in[3];
    const float* W_g    = (const float*)d_in[4];
    const float* b_h    = (const float*)d_in[5];
    const float* gamma  = (const float*)d_in[6];
    const float* beta   = (const float*)d_in[7];

    float* outH = (float*)d_out;                 // h_t: 128*1024
    float* outA = (float*)d_out + BATCH * DH;    // A_k: 128*1024*1024

    float* y0;  cudaGetSymbolAddress((void**)&y0, g_y0);
    float* y1;  cudaGetSymbolAddress((void**)&y1, g_y1);

    base_gemm_kernel<<<dim3(BATCH / 32, DH / 32), 256>>>(h_prev, z, W_h, W_g, b_h);

    // L2 chaining: conv ascending (normal stores) -> mv2 descending ->
    // mv3 ascending -> update descending. Each launch starts on the slice
    // of g_Ah its predecessor left in L2.
    matvec_conv_kernel<<<dim3(16, BATCH), 256>>>(A_prev, y0, gamma, beta);
    matvec_h_kernel<<<dim3(32, BATCH), 256>>>(y0, y1, gamma, beta, /*rev=*/1);
    matvec_h_kernel<<<dim3(32, BATCH), 256>>>(y1, y0, gamma, beta, /*rev=*/0);

    h_final_kernel<<<BATCH, 256>>>(y0, gamma, beta, outH);
    update_stream_kernel<<<dim3(128, BATCH), 256>>>(outH, outA);
}

// round 13
// speedup vs baseline: 1.0039x; 1.0039x over previous
#include <cuda_runtime.h>
#include <cuda_fp16.h>

#define BATCH 128
#define DG 512
#define DH 1024
#define LAM 0.95f
#define ETA 0.5f
#define LN_EPS 1e-5f

// Scratch (allocation-free)
__device__ float  g_base[BATCH * DH];
__device__ float  g_y0[BATCH * DH];
__device__ float  g_y1[BATCH * DH];
__device__ __half g_Ah[(size_t)BATCH * DH * DH];   // fp16 copy of A (268MB)

// ---------------------------------------------------------------------------
__device__ __forceinline__ float2 pack_h4(float4 v) {
    __half2 a = __floats2half2_rn(v.x, v.y);
    __half2 b = __floats2half2_rn(v.z, v.w);
    float2 r;
    r.x = __uint_as_float(*reinterpret_cast<unsigned int*>(&a));
    r.y = __uint_as_float(*reinterpret_cast<unsigned int*>(&b));
    return r;
}

__device__ __forceinline__ float dot8(uint4 v, float4 ha, float4 hb) {
    const __half2* p = reinterpret_cast<const __half2*>(&v);
    float2 f0 = __half22float2(p[0]);
    float2 f1 = __half22float2(p[1]);
    float2 f2 = __half22float2(p[2]);
    float2 f3 = __half22float2(p[3]);
    return f0.x * ha.x + f0.y * ha.y + f1.x * ha.z + f1.y * ha.w
         + f2.x * hb.x + f2.y * hb.y + f3.x * hb.z + f3.y * hb.w;
}

// unpack 4 halfs (uint2) to float4
__device__ __forceinline__ float4 unpack_h4(uint2 v) {
    __half2 lo = *reinterpret_cast<__half2*>(&v.x);
    __half2 hi = *reinterpret_cast<__half2*>(&v.y);
    float2 f0 = __half22float2(lo);
    float2 f1 = __half22float2(hi);
    float4 r; r.x = f0.x; r.y = f0.y; r.z = f1.x; r.w = f1.y;
    return r;
}

// ---------------------------------------------------------------------------
// Kernel 1: base = h_prev@Wh^T + z@Wg^T + bh.
// ---------------------------------------------------------------------------
__global__ void base_gemm_kernel(const float* __restrict__ Hp,
                                 const float* __restrict__ Z,
                                 const float* __restrict__ Wh,
                                 const float* __restrict__ Wg,
                                 const float* __restrict__ bh)
{
    __shared__ float Hs[32][33];
    __shared__ float Ws[32][33];

    const int tid = threadIdx.x;
    const int tx = tid & 15;
    const int ty = tid >> 4;
    const int bm0 = blockIdx.x * 32;
    const int n0  = blockIdx.y * 32;

    float acc00 = 0.f, acc01 = 0.f, acc10 = 0.f, acc11 = 0.f;

    for (int k0 = 0; k0 < DH + DG; k0 += 32) {
        const float* src;
        const float* wsrc;
        int K, kk0;
        if (k0 < DH) { src = Hp; wsrc = Wh; K = DH; kk0 = k0; }
        else         { src = Z;  wsrc = Wg; K = DG; kk0 = k0 - DH; }

        #pragma unroll
        for (int l = 0; l < 4; l++) {
            int idx = tid + l * 256;
            int r = idx >> 5, c = idx & 31;
            Hs[r][c] = src[(bm0 + r) * K + kk0 + c];
            Ws[r][c] = wsrc[(n0 + r) * K + kk0 + c];
        }
        __syncthreads();

        #pragma unroll
        for (int kk = 0; kk < 32; kk++) {
            float h0 = Hs[ty * 2][kk];
            float h1 = Hs[ty * 2 + 1][kk];
            float w0 = Ws[tx * 2][kk];
            float w1 = Ws[tx * 2 + 1][kk];
            acc00 += h0 * w0; acc01 += h0 * w1;
            acc10 += h1 * w0; acc11 += h1 * w1;
        }
        __syncthreads();
    }

    const int r0 = bm0 + ty * 2;
    const int c0 = n0 + tx * 2;
    const float bias0 = bh[c0];
    const float bias1 = bh[c0 + 1];
    g_base[r0 * DH + c0]           = acc00 + bias0;
    g_base[r0 * DH + c0 + 1]       = acc01 + bias1;
    g_base[(r0 + 1) * DH + c0]     = acc10 + bias0;
    g_base[(r0 + 1) * DH + c0 + 1] = acc11 + bias1;
}

// ---------------------------------------------------------------------------
// In-block LN+ReLU: 256 threads, h[b] (1024 floats) into s_h. Trailing sync.
// ---------------------------------------------------------------------------
__device__ __forceinline__ void compute_h(const float* __restrict__ base_b,
                                          const float* __restrict__ y_b,
                                          const float* __restrict__ gamma,
                                          const float* __restrict__ beta,
                                          float* __restrict__ s_h,
                                          float* __restrict__ s_red,
                                          int t)
{
    const int w = t >> 5, lane = t & 31;

    float4 x = reinterpret_cast<const float4*>(base_b)[t];
    if (y_b) {
        float4 y = reinterpret_cast<const float4*>(y_b)[t];
        x.x += y.x; x.y += y.y; x.z += y.z; x.w += y.w;
    }
    float s  = (x.x + x.y) + (x.z + x.w);
    float ss = fmaf(x.x, x.x, x.y * x.y) + fmaf(x.z, x.z, x.w * x.w);

    #pragma unroll
    for (int o = 16; o > 0; o >>= 1) {
        s  += __shfl_xor_sync(0xffffffffu, s,  o);
        ss += __shfl_xor_sync(0xffffffffu, ss, o);
    }
    if (lane == 0) { s_red[w] = s; s_red[8 + w] = ss; }
    __syncthreads();
    if (t < 32) {
        float a = (lane < 8) ? s_red[lane]     : 0.f;
        float c = (lane < 8) ? s_red[8 + lane] : 0.f;
        #pragma unroll
        for (int o = 4; o > 0; o >>= 1) {
            a += __shfl_xor_sync(0xffffffffu, a, o);
            c += __shfl_xor_sync(0xffffffffu, c, o);
        }
        if (lane == 0) { s_red[0] = a; s_red[1] = c; }
    }
    __syncthreads();

    const float mu   = s_red[0] * (1.0f / DH);
    const float var  = s_red[1] * (1.0f / DH) - mu * mu;
    const float rstd = rsqrtf(var + LN_EPS);

    float4 g  = reinterpret_cast<const float4*>(gamma)[t];
    float4 be = reinterpret_cast<const float4*>(beta)[t];
    float4 h;
    h.x = fmaxf(0.f, (x.x - mu) * rstd * g.x + be.x);
    h.y = fmaxf(0.f, (x.y - mu) * rstd * g.y + be.y);
    h.z = fmaxf(0.f, (x.z - mu) * rstd * g.z + be.z);
    h.w = fmaxf(0.f, (x.w - mu) * rstd * g.w + be.w);
    reinterpret_cast<float4*>(s_h)[t] = h;
    __syncthreads();
}

// ---------------------------------------------------------------------------
// Kernel 2: mv1 + fp16 conversion.
// h1 = relu(LN(base)); y = A@h1 in fp32; stream fp16 copy of A to g_Ah.
// grid = (16 chunks, 128 batches), 256 thr.
// ---------------------------------------------------------------------------
__global__ __launch_bounds__(256)
void matvec_conv_kernel(const float* __restrict__ A,
                        float* __restrict__ yout,
                        const float* __restrict__ gamma,
                        const float* __restrict__ beta)
{
    __shared__ float s_h[DH];
    __shared__ float s_red[16];

    const int b = blockIdx.y;
    const int chunk = blockIdx.x;
    const int t = threadIdx.x;
    const int w = t >> 5, lane = t & 31;

    compute_h(g_base + b * DH, nullptr, gamma, beta, s_h, s_red, t);

    const float4* __restrict__ Ab =
        reinterpret_cast<const float4*>(A + (size_t)b * DH * DH);
    const float4* h4 = reinterpret_cast<const float4*>(s_h);

    #pragma unroll
    for (int g = 0; g < 2; g++) {
        const int r0 = chunk * 64 + w * 8 + g * 4;
        const float4* Ar0 = Ab + (size_t)r0 * 256;
        float2* __restrict__ Oh0 =
            reinterpret_cast<float2*>(g_Ah + ((size_t)b * DH + r0) * DH);

        float a0 = 0.f, a1 = 0.f, a2 = 0.f, a3 = 0.f;
        #pragma unroll
        for (int it = 0; it < 8; it++) {
            float4 v0 = __ldcs(Ar0 + lane + it * 32);
            float4 v1 = __ldcs(Ar0 + 256 + lane + it * 32);
            float4 v2 = __ldcs(Ar0 + 512 + lane + it * 32);
            float4 v3 = __ldcs(Ar0 + 768 + lane + it * 32);
            float4 hv = h4[lane + it * 32];
            a0 += v0.x * hv.x + v0.y * hv.y + v0.z * hv.z + v0.w * hv.w;
            a1 += v1.x * hv.x + v1.y * hv.y + v1.z * hv.z + v1.w * hv.w;
            a2 += v2.x * hv.x + v2.y * hv.y + v2.z * hv.z + v2.w * hv.w;
            a3 += v3.x * hv.x + v3.y * hv.y + v3.z * hv.z + v3.w * hv.w;
            __stcs(Oh0 + lane + it * 32,       pack_h4(v0));
            __stcs(Oh0 + 256 + lane + it * 32, pack_h4(v1));
            __stcs(Oh0 + 512 + lane + it * 32, pack_h4(v2));
            __stcs(Oh0 + 768 + lane + it * 32, pack_h4(v3));
        }
        #pragma unroll
        for (int o = 16; o > 0; o >>= 1) {
            a0 += __shfl_xor_sync(0xffffffffu, a0, o);
            a1 += __shfl_xor_sync(0xffffffffu, a1, o);
            a2 += __shfl_xor_sync(0xffffffffu, a2, o);
            a3 += __shfl_xor_sync(0xffffffffu, a3, o);
        }
        if (lane == 0) {
            yout[b * DH + r0]     = a0;
            yout[b * DH + r0 + 1] = a1;
            yout[b * DH + r0 + 2] = a2;
            yout[b * DH + r0 + 3] = a3;
        }
    }
}

// ---------------------------------------------------------------------------
// Kernel 3 (x2): fp16 matvec. h = relu(LN(base + yin)); yout = Ah@h.
// grid = (32 chunks of 32 rows, 128 batches), 256 thr; one 4-row group/warp.
// ---------------------------------------------------------------------------
__global__ __launch_bounds__(256)
void matvec_h_kernel(const float* __restrict__ yin,
                     float* __restrict__ yout,
                     const float* __restrict__ gamma,
                     const float* __restrict__ beta)
{
    __shared__ float s_h[DH];
    __shared__ float s_red[16];

    const int b = blockIdx.y;
    const int chunk = blockIdx.x;
    const int t = threadIdx.x;
    const int w = t >> 5, lane = t & 31;

    compute_h(g_base + b * DH, yin + b * DH, gamma, beta, s_h, s_red, t);

    const float4* h4 = reinterpret_cast<const float4*>(s_h);

    const int r0 = chunk * 32 + w * 4;
    const uint4* __restrict__ R0 =
        reinterpret_cast<const uint4*>(g_Ah + ((size_t)b * DH + r0) * DH);

    float a0 = 0.f, a1 = 0.f, a2 = 0.f, a3 = 0.f;
    #pragma unroll
    for (int it = 0; it < 4; it++) {
        uint4 v0 = __ldcs(R0 + lane + it * 32);
        uint4 v1 = __ldcs(R0 + 128 + lane + it * 32);
        uint4 v2 = __ldcs(R0 + 256 + lane + it * 32);
        uint4 v3 = __ldcs(R0 + 384 + lane + it * 32);
        const int idx = (it * 32 + lane) * 2;
        float4 ha = h4[idx];
        float4 hb = h4[idx + 1];
        a0 += dot8(v0, ha, hb);
        a1 += dot8(v1, ha, hb);
        a2 += dot8(v2, ha, hb);
        a3 += dot8(v3, ha, hb);
    }
    #pragma unroll
    for (int o = 16; o > 0; o >>= 1) {
        a0 += __shfl_xor_sync(0xffffffffu, a0, o);
        a1 += __shfl_xor_sync(0xffffffffu, a1, o);
        a2 += __shfl_xor_sync(0xffffffffu, a2, o);
        a3 += __shfl_xor_sync(0xffffffffu, a3, o);
    }
    if (lane == 0) {
        yout[b * DH + r0]     = a0;
        yout[b * DH + r0 + 1] = a1;
        yout[b * DH + r0 + 2] = a2;
        yout[b * DH + r0 + 3] = a3;
    }
}

// ---------------------------------------------------------------------------
// Kernel 4: h3 = relu(LN(base + yin)) written straight into outH.
// ---------------------------------------------------------------------------
__global__ __launch_bounds__(256)
void h_final_kernel(const float* __restrict__ yin,
                    const float* __restrict__ gamma,
                    const float* __restrict__ beta,
                    float* __restrict__ outH)
{
    __shared__ float s_h[DH];
    __shared__ float s_red[16];
    const int b = blockIdx.x;
    const int t = threadIdx.x;

    compute_h(g_base + b * DH, yin + b * DH, gamma, beta, s_h, s_red, t);
    reinterpret_cast<float4*>(outH + b * DH)[t] =
        reinterpret_cast<const float4*>(s_h)[t];
}

// ---------------------------------------------------------------------------
// Kernel 5: pure-stream Hebbian update from fp16 A.
// 32 rows per block, 2-wave register pipeline: load wave k+1 is issued
// BEFORE draining wave k, so reads stay outstanding while stores issue.
// Coalesced uint2 loads at +t, coalesced float4 stores at +t.
// grid = (32 chunks of 32 rows, 128 batches), 256 thr.
// ---------------------------------------------------------------------------
__global__ __launch_bounds__(256)
void update_stream_kernel(const float* __restrict__ h3,   // = outH
                          float* __restrict__ outA)
{
    const int b = blockIdx.y;
    const int chunk = blockIdx.x;
    const int t = threadIdx.x;
    const int row0 = chunk * 32;

    const uint2* __restrict__ Ab =
        reinterpret_cast<const uint2*>(g_Ah + (size_t)b * DH * DH) +
        (size_t)row0 * 256;                       // 256 uint2 per row
    float4* __restrict__ Ob =
        reinterpret_cast<float4*>(outA + (size_t)b * DH * DH) +
        (size_t)row0 * 256;

    const float4 hv = __ldg(reinterpret_cast<const float4*>(h3 + b * DH) + t);

    float hr[32];
    #pragma unroll
    for (int r = 0; r < 32; r++)
        hr[r] = __ldg(h3 + b * DH + row0 + r) * ETA;

    uint2 cur[8], nxt[8];

    // prime wave 0
    #pragma unroll
    for (int r = 0; r < 8; r++)
        cur[r] = __ldcs(Ab + (size_t)r * 256 + t);

    #pragma unroll
    for (int wv = 0; wv < 4; wv++) {
        // issue next wave's loads BEFORE draining this one
        if (wv < 3) {
            const uint2* An = Ab + (size_t)(wv + 1) * 8 * 256 + t;
            #pragma unroll
            for (int r = 0; r < 8; r++)
                nxt[r] = __ldcs(An + (size_t)r * 256);
        }
        // drain current wave: unpack, fma, store
        float4* Ow = Ob + (size_t)wv * 8 * 256 + t;
        #pragma unroll
        for (int r = 0; r < 8; r++) {
            float4 a = unpack_h4(cur[r]);
            const float hi = hr[wv * 8 + r];
            float4 o;
            o.x = fmaf(LAM, a.x, hi * hv.x);
            o.y = fmaf(LAM, a.y, hi * hv.y);
            o.z = fmaf(LAM, a.z, hi * hv.z);
            o.w = fmaf(LAM, a.w, hi * hv.w);
            __stcs(Ow + (size_t)r * 256, o);
        }
        #pragma unroll
        for (int r = 0; r < 8; r++)
            cur[r] = nxt[r];
    }
}

// ---------------------------------------------------------------------------
extern "C" void kernel_launch(void* const* d_in, const int* in_sizes, int n_in,
                              void* d_out, int out_size)
{
    const float* z      = (const float*)d_in[0];
    const float* h_prev = (const float*)d_in[1];
    const float* A_prev = (const float*)d_in[2];
    const float* W_h    = (const float*)d_in[3];
    const float* W_g    = (const float*)d_in[4];
    const float* b_h    = (const float*)d_in[5];
    const float* gamma  = (const float*)d_in[6];
    const float* beta   = (const float*)d_in[7];

    float* outH = (float*)d_out;                 // h_t: 128*1024
    float* outA = (float*)d_out + BATCH * DH;    // A_k: 128*1024*1024

    float* y0;  cudaGetSymbolAddress((void**)&y0, g_y0);
    float* y1;  cudaGetSymbolAddress((void**)&y1, g_y1);

    base_gemm_kernel<<<dim3(BATCH / 32, DH / 32), 256>>>(h_prev, z, W_h, W_g, b_h);

    matvec_conv_kernel<<<dim3(16, BATCH), 256>>>(A_prev, y0, gamma, beta);
    matvec_h_kernel<<<dim3(32, BATCH), 256>>>(y0, y1, gamma, beta);
    matvec_h_kernel<<<dim3(32, BATCH), 256>>>(y1, y0, gamma, beta);

    h_final_kernel<<<BATCH, 256>>>(y0, gamma, beta, outH);
    update_stream_kernel<<<dim3(32, BATCH), 256>>>(outH, outA);
}

// round 14
// speedup vs baseline: 1.0498x; 1.0457x over previous
#include <cuda_runtime.h>
#include <cuda_fp16.h>

#define BATCH 128
#define HALF_B (BATCH / 2)
#define DG 512
#define DH 1024
#define LAM 0.95f
#define ETA 0.5f
#define LN_EPS 1e-5f

// Scratch (allocation-free)
__device__ float  g_base[BATCH * DH];
__device__ float  g_y0[BATCH * DH];
__device__ float  g_y1[BATCH * DH];
__device__ __half g_Ah[(size_t)BATCH * DH * DH];   // fp16 copy of A (268MB)

// ---------------------------------------------------------------------------
__device__ __forceinline__ float2 pack_h4(float4 v) {
    __half2 a = __floats2half2_rn(v.x, v.y);
    __half2 b = __floats2half2_rn(v.z, v.w);
    float2 r;
    r.x = __uint_as_float(*reinterpret_cast<unsigned int*>(&a));
    r.y = __uint_as_float(*reinterpret_cast<unsigned int*>(&b));
    return r;
}

__device__ __forceinline__ float dot8(uint4 v, float4 ha, float4 hb) {
    const __half2* p = reinterpret_cast<const __half2*>(&v);
    float2 f0 = __half22float2(p[0]);
    float2 f1 = __half22float2(p[1]);
    float2 f2 = __half22float2(p[2]);
    float2 f3 = __half22float2(p[3]);
    return f0.x * ha.x + f0.y * ha.y + f1.x * ha.z + f1.y * ha.w
         + f2.x * hb.x + f2.y * hb.y + f3.x * hb.z + f3.y * hb.w;
}

// unpack 4 halfs (uint2) to float4
__device__ __forceinline__ float4 unpack_h4(uint2 v) {
    __half2 lo = *reinterpret_cast<__half2*>(&v.x);
    __half2 hi = *reinterpret_cast<__half2*>(&v.y);
    float2 f0 = __half22float2(lo);
    float2 f1 = __half22float2(hi);
    float4 r; r.x = f0.x; r.y = f0.y; r.z = f1.x; r.w = f1.y;
    return r;
}

// ---------------------------------------------------------------------------
// Kernel 1: base = h_prev@Wh^T + z@Wg^T + bh. (all batches)
// ---------------------------------------------------------------------------
__global__ void base_gemm_kernel(const float* __restrict__ Hp,
                                 const float* __restrict__ Z,
                                 const float* __restrict__ Wh,
                                 const float* __restrict__ Wg,
                                 const float* __restrict__ bh)
{
    __shared__ float Hs[32][33];
    __shared__ float Ws[32][33];

    const int tid = threadIdx.x;
    const int tx = tid & 15;
    const int ty = tid >> 4;
    const int bm0 = blockIdx.x * 32;
    const int n0  = blockIdx.y * 32;

    float acc00 = 0.f, acc01 = 0.f, acc10 = 0.f, acc11 = 0.f;

    for (int k0 = 0; k0 < DH + DG; k0 += 32) {
        const float* src;
        const float* wsrc;
        int K, kk0;
        if (k0 < DH) { src = Hp; wsrc = Wh; K = DH; kk0 = k0; }
        else         { src = Z;  wsrc = Wg; K = DG; kk0 = k0 - DH; }

        #pragma unroll
        for (int l = 0; l < 4; l++) {
            int idx = tid + l * 256;
            int r = idx >> 5, c = idx & 31;
            Hs[r][c] = src[(bm0 + r) * K + kk0 + c];
            Ws[r][c] = wsrc[(n0 + r) * K + kk0 + c];
        }
        __syncthreads();

        #pragma unroll
        for (int kk = 0; kk < 32; kk++) {
            float h0 = Hs[ty * 2][kk];
            float h1 = Hs[ty * 2 + 1][kk];
            float w0 = Ws[tx * 2][kk];
            float w1 = Ws[tx * 2 + 1][kk];
            acc00 += h0 * w0; acc01 += h0 * w1;
            acc10 += h1 * w0; acc11 += h1 * w1;
        }
        __syncthreads();
    }

    const int r0 = bm0 + ty * 2;
    const int c0 = n0 + tx * 2;
    const float bias0 = bh[c0];
    const float bias1 = bh[c0 + 1];
    g_base[r0 * DH + c0]           = acc00 + bias0;
    g_base[r0 * DH + c0 + 1]       = acc01 + bias1;
    g_base[(r0 + 1) * DH + c0]     = acc10 + bias0;
    g_base[(r0 + 1) * DH + c0 + 1] = acc11 + bias1;
}

// ---------------------------------------------------------------------------
// In-block LN+ReLU: 256 threads, h[b] (1024 floats) into s_h. Trailing sync.
// ---------------------------------------------------------------------------
__device__ __forceinline__ void compute_h(const float* __restrict__ base_b,
                                          const float* __restrict__ y_b,
                                          const float* __restrict__ gamma,
                                          const float* __restrict__ beta,
                                          float* __restrict__ s_h,
                                          float* __restrict__ s_red,
                                          int t)
{
    const int w = t >> 5, lane = t & 31;

    float4 x = reinterpret_cast<const float4*>(base_b)[t];
    if (y_b) {
        float4 y = reinterpret_cast<const float4*>(y_b)[t];
        x.x += y.x; x.y += y.y; x.z += y.z; x.w += y.w;
    }
    float s  = (x.x + x.y) + (x.z + x.w);
    float ss = fmaf(x.x, x.x, x.y * x.y) + fmaf(x.z, x.z, x.w * x.w);

    #pragma unroll
    for (int o = 16; o > 0; o >>= 1) {
        s  += __shfl_xor_sync(0xffffffffu, s,  o);
        ss += __shfl_xor_sync(0xffffffffu, ss, o);
    }
    if (lane == 0) { s_red[w] = s; s_red[8 + w] = ss; }
    __syncthreads();
    if (t < 32) {
        float a = (lane < 8) ? s_red[lane]     : 0.f;
        float c = (lane < 8) ? s_red[8 + lane] : 0.f;
        #pragma unroll
        for (int o = 4; o > 0; o >>= 1) {
            a += __shfl_xor_sync(0xffffffffu, a, o);
            c += __shfl_xor_sync(0xffffffffu, c, o);
        }
        if (lane == 0) { s_red[0] = a; s_red[1] = c; }
    }
    __syncthreads();

    const float mu   = s_red[0] * (1.0f / DH);
    const float var  = s_red[1] * (1.0f / DH) - mu * mu;
    const float rstd = rsqrtf(var + LN_EPS);

    float4 g  = reinterpret_cast<const float4*>(gamma)[t];
    float4 be = reinterpret_cast<const float4*>(beta)[t];
    float4 h;
    h.x = fmaxf(0.f, (x.x - mu) * rstd * g.x + be.x);
    h.y = fmaxf(0.f, (x.y - mu) * rstd * g.y + be.y);
    h.z = fmaxf(0.f, (x.z - mu) * rstd * g.z + be.z);
    h.w = fmaxf(0.f, (x.w - mu) * rstd * g.w + be.w);
    reinterpret_cast<float4*>(s_h)[t] = h;
    __syncthreads();
}

// ---------------------------------------------------------------------------
// Kernel 2: mv1 + fp16 conversion (batches [b0, b0+gridDim.y)).
// ---------------------------------------------------------------------------
__global__ __launch_bounds__(256)
void matvec_conv_kernel(const float* __restrict__ A,
                        float* __restrict__ yout,
                        const float* __restrict__ gamma,
                        const float* __restrict__ beta,
                        int b0)
{
    __shared__ float s_h[DH];
    __shared__ float s_red[16];

    const int b = b0 + blockIdx.y;
    const int chunk = blockIdx.x;
    const int t = threadIdx.x;
    const int w = t >> 5, lane = t & 31;

    compute_h(g_base + b * DH, nullptr, gamma, beta, s_h, s_red, t);

    const float4* __restrict__ Ab =
        reinterpret_cast<const float4*>(A + (size_t)b * DH * DH);
    const float4* h4 = reinterpret_cast<const float4*>(s_h);

    #pragma unroll
    for (int g = 0; g < 2; g++) {
        const int r0 = chunk * 64 + w * 8 + g * 4;
        const float4* Ar0 = Ab + (size_t)r0 * 256;
        float2* __restrict__ Oh0 =
            reinterpret_cast<float2*>(g_Ah + ((size_t)b * DH + r0) * DH);

        float a0 = 0.f, a1 = 0.f, a2 = 0.f, a3 = 0.f;
        #pragma unroll
        for (int it = 0; it < 8; it++) {
            float4 v0 = __ldcs(Ar0 + lane + it * 32);
            float4 v1 = __ldcs(Ar0 + 256 + lane + it * 32);
            float4 v2 = __ldcs(Ar0 + 512 + lane + it * 32);
            float4 v3 = __ldcs(Ar0 + 768 + lane + it * 32);
            float4 hv = h4[lane + it * 32];
            a0 += v0.x * hv.x + v0.y * hv.y + v0.z * hv.z + v0.w * hv.w;
            a1 += v1.x * hv.x + v1.y * hv.y + v1.z * hv.z + v1.w * hv.w;
            a2 += v2.x * hv.x + v2.y * hv.y + v2.z * hv.z + v2.w * hv.w;
            a3 += v3.x * hv.x + v3.y * hv.y + v3.z * hv.z + v3.w * hv.w;
            __stcs(Oh0 + lane + it * 32,       pack_h4(v0));
            __stcs(Oh0 + 256 + lane + it * 32, pack_h4(v1));
            __stcs(Oh0 + 512 + lane + it * 32, pack_h4(v2));
            __stcs(Oh0 + 768 + lane + it * 32, pack_h4(v3));
        }
        #pragma unroll
        for (int o = 16; o > 0; o >>= 1) {
            a0 += __shfl_xor_sync(0xffffffffu, a0, o);
            a1 += __shfl_xor_sync(0xffffffffu, a1, o);
            a2 += __shfl_xor_sync(0xffffffffu, a2, o);
            a3 += __shfl_xor_sync(0xffffffffu, a3, o);
        }
        if (lane == 0) {
            yout[b * DH + r0]     = a0;
            yout[b * DH + r0 + 1] = a1;
            yout[b * DH + r0 + 2] = a2;
            yout[b * DH + r0 + 3] = a3;
        }
    }
}

// ---------------------------------------------------------------------------
// Kernel 3 (x2 per half): fp16 matvec. h = relu(LN(base+yin)); yout = Ah@h.
// ---------------------------------------------------------------------------
__global__ __launch_bounds__(256)
void matvec_h_kernel(const float* __restrict__ yin,
                     float* __restrict__ yout,
                     const float* __restrict__ gamma,
                     const float* __restrict__ beta,
                     int b0)
{
    __shared__ float s_h[DH];
    __shared__ float s_red[16];

    const int b = b0 + blockIdx.y;
    const int chunk = blockIdx.x;
    const int t = threadIdx.x;
    const int w = t >> 5, lane = t & 31;

    compute_h(g_base + b * DH, yin + b * DH, gamma, beta, s_h, s_red, t);

    const float4* h4 = reinterpret_cast<const float4*>(s_h);

    const int r0 = chunk * 32 + w * 4;
    const uint4* __restrict__ R0 =
        reinterpret_cast<const uint4*>(g_Ah + ((size_t)b * DH + r0) * DH);

    float a0 = 0.f, a1 = 0.f, a2 = 0.f, a3 = 0.f;
    #pragma unroll
    for (int it = 0; it < 4; it++) {
        uint4 v0 = __ldcs(R0 + lane + it * 32);
        uint4 v1 = __ldcs(R0 + 128 + lane + it * 32);
        uint4 v2 = __ldcs(R0 + 256 + lane + it * 32);
        uint4 v3 = __ldcs(R0 + 384 + lane + it * 32);
        const int idx = (it * 32 + lane) * 2;
        float4 ha = h4[idx];
        float4 hb = h4[idx + 1];
        a0 += dot8(v0, ha, hb);
        a1 += dot8(v1, ha, hb);
        a2 += dot8(v2, ha, hb);
        a3 += dot8(v3, ha, hb);
    }
    #pragma unroll
    for (int o = 16; o > 0; o >>= 1) {
        a0 += __shfl_xor_sync(0xffffffffu, a0, o);
        a1 += __shfl_xor_sync(0xffffffffu, a1, o);
        a2 += __shfl_xor_sync(0xffffffffu, a2, o);
        a3 += __shfl_xor_sync(0xffffffffu, a3, o);
    }
    if (lane == 0) {
        yout[b * DH + r0]     = a0;
        yout[b * DH + r0 + 1] = a1;
        yout[b * DH + r0 + 2] = a2;
        yout[b * DH + r0 + 3] = a3;
    }
}

// ---------------------------------------------------------------------------
// Kernel 4: h3 = relu(LN(base + yin)) written straight into outH.
// ---------------------------------------------------------------------------
__global__ __launch_bounds__(256)
void h_final_kernel(const float* __restrict__ yin,
                    const float* __restrict__ gamma,
                    const float* __restrict__ beta,
                    float* __restrict__ outH,
                    int b0)
{
    __shared__ float s_h[DH];
    __shared__ float s_red[16];
    const int b = b0 + blockIdx.x;
    const int t = threadIdx.x;

    compute_h(g_base + b * DH, yin + b * DH, gamma, beta, s_h, s_red, t);
    reinterpret_cast<float4*>(outH + b * DH)[t] =
        reinterpret_cast<const float4*>(s_h)[t];
}

// ---------------------------------------------------------------------------
// Kernel 5: pure-stream Hebbian update from fp16 A (R11 proven layout:
// coalesced uint2 loads at +t, float4 stores at +t, 8 rows, loads upfront).
// ---------------------------------------------------------------------------
__global__ __launch_bounds__(256)
void update_stream_kernel(const float* __restrict__ h3,   // = outH
                          float* __restrict__ outA,
                          int b0)
{
    const int b = b0 + blockIdx.y;
    const int chunk = blockIdx.x;
    const int t = threadIdx.x;
    const int row0 = chunk * 8;

    const uint2* __restrict__ Ab =
        reinterpret_cast<const uint2*>(g_Ah + (size_t)b * DH * DH) +
        (size_t)row0 * 256;                       // 256 uint2 per row
    float4* __restrict__ Ob =
        reinterpret_cast<float4*>(outA + (size_t)b * DH * DH) +
        (size_t)row0 * 256;

    const float4 hv = __ldg(reinterpret_cast<const float4*>(h3 + b * DH) + t);

    float hr[8];
    #pragma unroll
    for (int r = 0; r < 8; r++)
        hr[r] = __ldg(h3 + b * DH + row0 + r) * ETA;

    uint2 c[8];
    #pragma unroll
    for (int r = 0; r < 8; r++)
        c[r] = __ldcs(Ab + (size_t)r * 256 + t);

    #pragma unroll
    for (int r = 0; r < 8; r++) {
        float4 a = unpack_h4(c[r]);
        const float hi = hr[r];
        float4 o;
        o.x = fmaf(LAM, a.x, hi * hv.x);
        o.y = fmaf(LAM, a.y, hi * hv.y);
        o.z = fmaf(LAM, a.z, hi * hv.z);
        o.w = fmaf(LAM, a.w, hi * hv.w);
        __stcs(Ob + (size_t)r * 256 + t, o);
    }
}

// ---------------------------------------------------------------------------
extern "C" void kernel_launch(void* const* d_in, const int* in_sizes, int n_in,
                              void* d_out, int out_size)
{
    const float* z      = (const float*)d_in[0];
    const float* h_prev = (const float*)d_in[1];
    const float* A_prev = (const float*)d_in[2];
    const float* W_h    = (const float*)d_in[3];
    const float* W_g    = (const float*)d_in[4];
    const float* b_h    = (const float*)d_in[5];
    const float* gamma  = (const float*)d_in[6];
    const float* beta   = (const float*)d_in[7];

    float* outH = (float*)d_out;                 // h_t: 128*1024
    float* outA = (float*)d_out + BATCH * DH;    // A_k: 128*1024*1024

    float* y0;  cudaGetSymbolAddress((void**)&y0, g_y0);
    float* y1;  cudaGetSymbolAddress((void**)&y1, g_y1);

    // One-time stream/event setup. Happens on the FIRST (non-capture)
    // correctness call; by graph-capture time these already exist, so no
    // resources are created during capture. Launch work is identical on
    // every call (deterministic).
    static cudaStream_t s2 = nullptr;
    static cudaEvent_t evFork = nullptr, evJoin = nullptr;
    if (s2 == nullptr) {
        cudaStreamCreateWithFlags(&s2, cudaStreamNonBlocking);
        cudaEventCreateWithFlags(&evFork, cudaEventDisableTiming);
        cudaEventCreateWithFlags(&evJoin, cudaEventDisableTiming);
    }

    // base for ALL batches on the main (capture) stream
    base_gemm_kernel<<<dim3(BATCH / 32, DH / 32), 256>>>(h_prev, z, W_h, W_g, b_h);

    // fork: second half of the batch range runs on s2
    cudaEventRecord(evFork, 0);
    cudaStreamWaitEvent(s2, evFork, 0);

    // ---- chain A: batches [0, 64) on the main stream ----
    matvec_conv_kernel<<<dim3(16, HALF_B), 256>>>(A_prev, y0, gamma, beta, 0);
    matvec_h_kernel<<<dim3(32, HALF_B), 256>>>(y0, y1, gamma, beta, 0);
    matvec_h_kernel<<<dim3(32, HALF_B), 256>>>(y1, y0, gamma, beta, 0);
    h_final_kernel<<<HALF_B, 256>>>(y0, gamma, beta, outH, 0);
    update_stream_kernel<<<dim3(128, HALF_B), 256>>>(outH, outA, 0);

    // ---- chain B: batches [64, 128) on s2 ----
    matvec_conv_kernel<<<dim3(16, HALF_B), 256, 0, s2>>>(A_prev, y0, gamma, beta, HALF_B);
    matvec_h_kernel<<<dim3(32, HALF_B), 256, 0, s2>>>(y0, y1, gamma, beta, HALF_B);
    matvec_h_kernel<<<dim3(32, HALF_B), 256, 0, s2>>>(y1, y0, gamma, beta, HALF_B);
    h_final_kernel<<<HALF_B, 256, 0, s2>>>(y0, gamma, beta, outH, HALF_B);
    update_stream_kernel<<<dim3(128, HALF_B), 256, 0, s2>>>(outH, outA, HALF_B);

    // join: main stream waits for chain B
    cudaEventRecord(evJoin, s2);
    cudaStreamWaitEvent(0, evJoin, 0);
}

// round 15
// speedup vs baseline: 1.0639x; 1.0135x over previous
#include <cuda_runtime.h>
#include <cuda_fp16.h>

#define BATCH 128
#define NCHAIN 4
#define CHAIN_B (BATCH / NCHAIN)   // 32 batches per chain
#define DG 512
#define DH 1024
#define LAM 0.95f
#define ETA 0.5f
#define LN_EPS 1e-5f

// Scratch (allocation-free)
__device__ float  g_base[BATCH * DH];
__device__ float  g_y0[BATCH * DH];
__device__ float  g_y1[BATCH * DH];
__device__ __half g_Ah[(size_t)BATCH * DH * DH];   // fp16 copy of A (268MB)

// ---------------------------------------------------------------------------
__device__ __forceinline__ float2 pack_h4(float4 v) {
    __half2 a = __floats2half2_rn(v.x, v.y);
    __half2 b = __floats2half2_rn(v.z, v.w);
    float2 r;
    r.x = __uint_as_float(*reinterpret_cast<unsigned int*>(&a));
    r.y = __uint_as_float(*reinterpret_cast<unsigned int*>(&b));
    return r;
}

__device__ __forceinline__ float dot8(uint4 v, float4 ha, float4 hb) {
    const __half2* p = reinterpret_cast<const __half2*>(&v);
    float2 f0 = __half22float2(p[0]);
    float2 f1 = __half22float2(p[1]);
    float2 f2 = __half22float2(p[2]);
    float2 f3 = __half22float2(p[3]);
    return f0.x * ha.x + f0.y * ha.y + f1.x * ha.z + f1.y * ha.w
         + f2.x * hb.x + f2.y * hb.y + f3.x * hb.z + f3.y * hb.w;
}

// unpack 4 halfs (uint2) to float4
__device__ __forceinline__ float4 unpack_h4(uint2 v) {
    __half2 lo = *reinterpret_cast<__half2*>(&v.x);
    __half2 hi = *reinterpret_cast<__half2*>(&v.y);
    float2 f0 = __half22float2(lo);
    float2 f1 = __half22float2(hi);
    float4 r; r.x = f0.x; r.y = f0.y; r.z = f1.x; r.w = f1.y;
    return r;
}

// ---------------------------------------------------------------------------
// Kernel 1: base = h_prev@Wh^T + z@Wg^T + bh. (all batches)
// ---------------------------------------------------------------------------
__global__ void base_gemm_kernel(const float* __restrict__ Hp,
                                 const float* __restrict__ Z,
                                 const float* __restrict__ Wh,
                                 const float* __restrict__ Wg,
                                 const float* __restrict__ bh)
{
    __shared__ float Hs[32][33];
    __shared__ float Ws[32][33];

    const int tid = threadIdx.x;
    const int tx = tid & 15;
    const int ty = tid >> 4;
    const int bm0 = blockIdx.x * 32;
    const int n0  = blockIdx.y * 32;

    float acc00 = 0.f, acc01 = 0.f, acc10 = 0.f, acc11 = 0.f;

    for (int k0 = 0; k0 < DH + DG; k0 += 32) {
        const float* src;
        const float* wsrc;
        int K, kk0;
        if (k0 < DH) { src = Hp; wsrc = Wh; K = DH; kk0 = k0; }
        else         { src = Z;  wsrc = Wg; K = DG; kk0 = k0 - DH; }

        #pragma unroll
        for (int l = 0; l < 4; l++) {
            int idx = tid + l * 256;
            int r = idx >> 5, c = idx & 31;
            Hs[r][c] = src[(bm0 + r) * K + kk0 + c];
            Ws[r][c] = wsrc[(n0 + r) * K + kk0 + c];
        }
        __syncthreads();

        #pragma unroll
        for (int kk = 0; kk < 32; kk++) {
            float h0 = Hs[ty * 2][kk];
            float h1 = Hs[ty * 2 + 1][kk];
            float w0 = Ws[tx * 2][kk];
            float w1 = Ws[tx * 2 + 1][kk];
            acc00 += h0 * w0; acc01 += h0 * w1;
            acc10 += h1 * w0; acc11 += h1 * w1;
        }
        __syncthreads();
    }

    const int r0 = bm0 + ty * 2;
    const int c0 = n0 + tx * 2;
    const float bias0 = bh[c0];
    const float bias1 = bh[c0 + 1];
    g_base[r0 * DH + c0]           = acc00 + bias0;
    g_base[r0 * DH + c0 + 1]       = acc01 + bias1;
    g_base[(r0 + 1) * DH + c0]     = acc10 + bias0;
    g_base[(r0 + 1) * DH + c0 + 1] = acc11 + bias1;
}

// ---------------------------------------------------------------------------
// In-block LN+ReLU: 256 threads, h[b] (1024 floats) into s_h. Trailing sync.
// ---------------------------------------------------------------------------
__device__ __forceinline__ void compute_h(const float* __restrict__ base_b,
                                          const float* __restrict__ y_b,
                                          const float* __restrict__ gamma,
                                          const float* __restrict__ beta,
                                          float* __restrict__ s_h,
                                          float* __restrict__ s_red,
                                          int t)
{
    const int w = t >> 5, lane = t & 31;

    float4 x = reinterpret_cast<const float4*>(base_b)[t];
    if (y_b) {
        float4 y = reinterpret_cast<const float4*>(y_b)[t];
        x.x += y.x; x.y += y.y; x.z += y.z; x.w += y.w;
    }
    float s  = (x.x + x.y) + (x.z + x.w);
    float ss = fmaf(x.x, x.x, x.y * x.y) + fmaf(x.z, x.z, x.w * x.w);

    #pragma unroll
    for (int o = 16; o > 0; o >>= 1) {
        s  += __shfl_xor_sync(0xffffffffu, s,  o);
        ss += __shfl_xor_sync(0xffffffffu, ss, o);
    }
    if (lane == 0) { s_red[w] = s; s_red[8 + w] = ss; }
    __syncthreads();
    if (t < 32) {
        float a = (lane < 8) ? s_red[lane]     : 0.f;
        float c = (lane < 8) ? s_red[8 + lane] : 0.f;
        #pragma unroll
        for (int o = 4; o > 0; o >>= 1) {
            a += __shfl_xor_sync(0xffffffffu, a, o);
            c += __shfl_xor_sync(0xffffffffu, c, o);
        }
        if (lane == 0) { s_red[0] = a; s_red[1] = c; }
    }
    __syncthreads();

    const float mu   = s_red[0] * (1.0f / DH);
    const float var  = s_red[1] * (1.0f / DH) - mu * mu;
    const float rstd = rsqrtf(var + LN_EPS);

    float4 g  = reinterpret_cast<const float4*>(gamma)[t];
    float4 be = reinterpret_cast<const float4*>(beta)[t];
    float4 h;
    h.x = fmaxf(0.f, (x.x - mu) * rstd * g.x + be.x);
    h.y = fmaxf(0.f, (x.y - mu) * rstd * g.y + be.y);
    h.z = fmaxf(0.f, (x.z - mu) * rstd * g.z + be.z);
    h.w = fmaxf(0.f, (x.w - mu) * rstd * g.w + be.w);
    reinterpret_cast<float4*>(s_h)[t] = h;
    __syncthreads();
}

// ---------------------------------------------------------------------------
// Kernel 2: mv1 + fp16 conversion (batches [b0, b0+gridDim.y)).
// ---------------------------------------------------------------------------
__global__ __launch_bounds__(256)
void matvec_conv_kernel(const float* __restrict__ A,
                        float* __restrict__ yout,
                        const float* __restrict__ gamma,
                        const float* __restrict__ beta,
                        int b0)
{
    __shared__ float s_h[DH];
    __shared__ float s_red[16];

    const int b = b0 + blockIdx.y;
    const int chunk = blockIdx.x;
    const int t = threadIdx.x;
    const int w = t >> 5, lane = t & 31;

    compute_h(g_base + b * DH, nullptr, gamma, beta, s_h, s_red, t);

    const float4* __restrict__ Ab =
        reinterpret_cast<const float4*>(A + (size_t)b * DH * DH);
    const float4* h4 = reinterpret_cast<const float4*>(s_h);

    #pragma unroll
    for (int g = 0; g < 2; g++) {
        const int r0 = chunk * 64 + w * 8 + g * 4;
        const float4* Ar0 = Ab + (size_t)r0 * 256;
        float2* __restrict__ Oh0 =
            reinterpret_cast<float2*>(g_Ah + ((size_t)b * DH + r0) * DH);

        float a0 = 0.f, a1 = 0.f, a2 = 0.f, a3 = 0.f;
        #pragma unroll
        for (int it = 0; it < 8; it++) {
            float4 v0 = __ldcs(Ar0 + lane + it * 32);
            float4 v1 = __ldcs(Ar0 + 256 + lane + it * 32);
            float4 v2 = __ldcs(Ar0 + 512 + lane + it * 32);
            float4 v3 = __ldcs(Ar0 + 768 + lane + it * 32);
            float4 hv = h4[lane + it * 32];
            a0 += v0.x * hv.x + v0.y * hv.y + v0.z * hv.z + v0.w * hv.w;
            a1 += v1.x * hv.x + v1.y * hv.y + v1.z * hv.z + v1.w * hv.w;
            a2 += v2.x * hv.x + v2.y * hv.y + v2.z * hv.z + v2.w * hv.w;
            a3 += v3.x * hv.x + v3.y * hv.y + v3.z * hv.z + v3.w * hv.w;
            __stcs(Oh0 + lane + it * 32,       pack_h4(v0));
            __stcs(Oh0 + 256 + lane + it * 32, pack_h4(v1));
            __stcs(Oh0 + 512 + lane + it * 32, pack_h4(v2));
            __stcs(Oh0 + 768 + lane + it * 32, pack_h4(v3));
        }
        #pragma unroll
        for (int o = 16; o > 0; o >>= 1) {
            a0 += __shfl_xor_sync(0xffffffffu, a0, o);
            a1 += __shfl_xor_sync(0xffffffffu, a1, o);
            a2 += __shfl_xor_sync(0xffffffffu, a2, o);
            a3 += __shfl_xor_sync(0xffffffffu, a3, o);
        }
        if (lane == 0) {
            yout[b * DH + r0]     = a0;
            yout[b * DH + r0 + 1] = a1;
            yout[b * DH + r0 + 2] = a2;
            yout[b * DH + r0 + 3] = a3;
        }
    }
}

// ---------------------------------------------------------------------------
// Kernel 3 (x2 per chain): fp16 matvec. h = relu(LN(base+yin)); yout = Ah@h.
// ---------------------------------------------------------------------------
__global__ __launch_bounds__(256)
void matvec_h_kernel(const float* __restrict__ yin,
                     float* __restrict__ yout,
                     const float* __restrict__ gamma,
                     const float* __restrict__ beta,
                     int b0)
{
    __shared__ float s_h[DH];
    __shared__ float s_red[16];

    const int b = b0 + blockIdx.y;
    const int chunk = blockIdx.x;
    const int t = threadIdx.x;
    const int w = t >> 5, lane = t & 31;

    compute_h(g_base + b * DH, yin + b * DH, gamma, beta, s_h, s_red, t);

    const float4* h4 = reinterpret_cast<const float4*>(s_h);

    const int r0 = chunk * 32 + w * 4;
    const uint4* __restrict__ R0 =
        reinterpret_cast<const uint4*>(g_Ah + ((size_t)b * DH + r0) * DH);

    float a0 = 0.f, a1 = 0.f, a2 = 0.f, a3 = 0.f;
    #pragma unroll
    for (int it = 0; it < 4; it++) {
        uint4 v0 = __ldcs(R0 + lane + it * 32);
        uint4 v1 = __ldcs(R0 + 128 + lane + it * 32);
        uint4 v2 = __ldcs(R0 + 256 + lane + it * 32);
        uint4 v3 = __ldcs(R0 + 384 + lane + it * 32);
        const int idx = (it * 32 + lane) * 2;
        float4 ha = h4[idx];
        float4 hb = h4[idx + 1];
        a0 += dot8(v0, ha, hb);
        a1 += dot8(v1, ha, hb);
        a2 += dot8(v2, ha, hb);
        a3 += dot8(v3, ha, hb);
    }
    #pragma unroll
    for (int o = 16; o > 0; o >>= 1) {
        a0 += __shfl_xor_sync(0xffffffffu, a0, o);
        a1 += __shfl_xor_sync(0xffffffffu, a1, o);
        a2 += __shfl_xor_sync(0xffffffffu, a2, o);
        a3 += __shfl_xor_sync(0xffffffffu, a3, o);
    }
    if (lane == 0) {
        yout[b * DH + r0]     = a0;
        yout[b * DH + r0 + 1] = a1;
        yout[b * DH + r0 + 2] = a2;
        yout[b * DH + r0 + 3] = a3;
    }
}

// ---------------------------------------------------------------------------
// Kernel 4: h3 = relu(LN(base + yin)) written straight into outH.
// ---------------------------------------------------------------------------
__global__ __launch_bounds__(256)
void h_final_kernel(const float* __restrict__ yin,
                    const float* __restrict__ gamma,
                    const float* __restrict__ beta,
                    float* __restrict__ outH,
                    int b0)
{
    __shared__ float s_h[DH];
    __shared__ float s_red[16];
    const int b = b0 + blockIdx.x;
    const int t = threadIdx.x;

    compute_h(g_base + b * DH, yin + b * DH, gamma, beta, s_h, s_red, t);
    reinterpret_cast<float4*>(outH + b * DH)[t] =
        reinterpret_cast<const float4*>(s_h)[t];
}

// ---------------------------------------------------------------------------
// Kernel 5: pure-stream Hebbian update from fp16 A (coalesced uint2 loads
// at +t, float4 stores at +t, 8 rows per block, loads upfront).
// ---------------------------------------------------------------------------
__global__ __launch_bounds__(256)
void update_stream_kernel(const float* __restrict__ h3,   // = outH
                          float* __restrict__ outA,
                          int b0)
{
    const int b = b0 + blockIdx.y;
    const int chunk = blockIdx.x;
    const int t = threadIdx.x;
    const int row0 = chunk * 8;

    const uint2* __restrict__ Ab =
        reinterpret_cast<const uint2*>(g_Ah + (size_t)b * DH * DH) +
        (size_t)row0 * 256;                       // 256 uint2 per row
    float4* __restrict__ Ob =
        reinterpret_cast<float4*>(outA + (size_t)b * DH * DH) +
        (size_t)row0 * 256;

    const float4 hv = __ldg(reinterpret_cast<const float4*>(h3 + b * DH) + t);

    float hr[8];
    #pragma unroll
    for (int r = 0; r < 8; r++)
        hr[r] = __ldg(h3 + b * DH + row0 + r) * ETA;

    uint2 c[8];
    #pragma unroll
    for (int r = 0; r < 8; r++)
        c[r] = __ldcs(Ab + (size_t)r * 256 + t);

    #pragma unroll
    for (int r = 0; r < 8; r++) {
        float4 a = unpack_h4(c[r]);
        const float hi = hr[r];
        float4 o;
        o.x = fmaf(LAM, a.x, hi * hv.x);
        o.y = fmaf(LAM, a.y, hi * hv.y);
        o.z = fmaf(LAM, a.z, hi * hv.z);
        o.w = fmaf(LAM, a.w, hi * hv.w);
        __stcs(Ob + (size_t)r * 256 + t, o);
    }
}

// ---------------------------------------------------------------------------
extern "C" void kernel_launch(void* const* d_in, const int* in_sizes, int n_in,
                              void* d_out, int out_size)
{
    const float* z      = (const float*)d_in[0];
    const float* h_prev = (const float*)d_in[1];
    const float* A_prev = (const float*)d_in[2];
    const float* W_h    = (const float*)d_in[3];
    const float* W_g    = (const float*)d_in[4];
    const float* b_h    = (const float*)d_in[5];
    const float* gamma  = (const float*)d_in[6];
    const float* beta   = (const float*)d_in[7];

    float* outH = (float*)d_out;                 // h_t: 128*1024
    float* outA = (float*)d_out + BATCH * DH;    // A_k: 128*1024*1024

    float* y0;  cudaGetSymbolAddress((void**)&y0, g_y0);
    float* y1;  cudaGetSymbolAddress((void**)&y1, g_y1);

    // One-time stream/event setup (on the first, non-capture call).
    static cudaStream_t sx[NCHAIN - 1] = {};
    static cudaEvent_t evFork = nullptr;
    static cudaEvent_t evJoin[NCHAIN - 1] = {};
    if (sx[0] == nullptr) {
        for (int i = 0; i < NCHAIN - 1; i++) {
            cudaStreamCreateWithFlags(&sx[i], cudaStreamNonBlocking);
            cudaEventCreateWithFlags(&evJoin[i], cudaEventDisableTiming);
        }
        cudaEventCreateWithFlags(&evFork, cudaEventDisableTiming);
    }

    // base for ALL batches on the main (capture) stream
    base_gemm_kernel<<<dim3(BATCH / 32, DH / 32), 256>>>(h_prev, z, W_h, W_g, b_h);

    // fork
    cudaEventRecord(evFork, 0);
    for (int i = 0; i < NCHAIN - 1; i++)
        cudaStreamWaitEvent(sx[i], evFork, 0);

    // chain 0 on the main stream; chains 1..3 on side streams
    for (int ch = 0; ch < NCHAIN; ch++) {
        cudaStream_t st = (ch == 0) ? (cudaStream_t)0 : sx[ch - 1];
        const int b0 = ch * CHAIN_B;
        matvec_conv_kernel<<<dim3(16, CHAIN_B), 256, 0, st>>>(A_prev, y0, gamma, beta, b0);
        matvec_h_kernel<<<dim3(32, CHAIN_B), 256, 0, st>>>(y0, y1, gamma, beta, b0);
        matvec_h_kernel<<<dim3(32, CHAIN_B), 256, 0, st>>>(y1, y0, gamma, beta, b0);
        h_final_kernel<<<CHAIN_B, 256, 0, st>>>(y0, gamma, beta, outH, b0);
        update_stream_kernel<<<dim3(128, CHAIN_B), 256, 0, st>>>(outH, outA, b0);
    }

    // join
    for (int i = 0; i < NCHAIN - 1; i++) {
        cudaEventRecord(evJoin[i], sx[i]);
        cudaStreamWaitEvent(0, evJoin[i], 0);
    }
}